// round 17
// baseline (speedup 1.0000x reference)
#include <cuda_runtime.h>
#include <cstdint>

// QuantumCircuitSimulator2: 24 qubits, 8 steps of 4-qubit (16x16 complex) gates.
// One gate per kernel, one 16-amplitude group per thread. Karatsuba complex
// matvec (A=gr, B=gr+gi, C=gi-gr) on fma.rn.f32x2, tables + targets in
// __constant__ memory.
// This round: j-BLOCKED (4 quarters of 4 outputs). State streams through 6
// live u64 per k-chunk instead of a 48-reg array -> ~56 regs ->
// __launch_bounds__(128, 9) -> 36 warps/SM. State re-gathered per quarter
// (passes 2-4 are L1 hits; per-SM set 144 KB < 228 KB L1).

#define NQ 24
#define NSTATE (1u << NQ)
#define NGROUPS (1u << (NQ - 4))     // 2^20
#define NSTEPS 8

typedef unsigned long long u64;

// interleaved scratch state (float2 per amplitude) — static device array
__device__ __align__(16) float QS_scratch[1u << 25];
// staging for Karatsuba tables + normalized targets before constant upload
__device__ __align__(16) float QS_tables[NSTEPS * 768];
__device__ int QS_tnorm[32];

// Karatsuba tables [step][3][16][16] = 24 KB, targets [8][4] ints
__constant__ __align__(16) float cGK[NSTEPS * 768];
__constant__ int cT[32];

__device__ __forceinline__ void fma2_acc(u64& acc, u64 a, u64 b) {
    asm("fma.rn.f32x2 %0, %1, %2, %0;" : "+l"(acc) : "l"(a), "l"(b));
}
__device__ __forceinline__ u64 mul2(u64 a, u64 b) {
    u64 d;
    asm("mul.rn.f32x2 %0, %1, %2;" : "=l"(d) : "l"(a), "l"(b));
    return d;
}
__device__ __forceinline__ u64 add2(u64 a, u64 b) {
    u64 d;
    asm("add.rn.f32x2 %0, %1, %2;" : "=l"(d) : "l"(a), "l"(b));
    return d;
}
__device__ __forceinline__ u64 pack2(float lo, float hi) {
    u64 d;
    asm("mov.b64 %0, {%1, %2};" : "=l"(d) : "f"(lo), "f"(hi));
    return d;
}
__device__ __forceinline__ void unpack2(u64 v, float& lo, float& hi) {
    asm("mov.b64 {%0, %1}, %2;" : "=f"(lo), "=f"(hi) : "l"(v));
}

// Build Karatsuba tables for all steps + normalize targets to int32.
__global__ void qprep_kernel(const float* __restrict__ gates,
                             const int* __restrict__ targets_raw) {
    int step = blockIdx.x;
    const float* g = gates + (size_t)step * 512;
    for (int i = threadIdx.x; i < 768; i += blockDim.x) {
        int t = i >> 8;
        int idx = i & 255;
        float gr = g[idx];
        float gi = g[256 + idx];
        QS_tables[step * 768 + i] =
            (t == 0) ? gr : ((t == 1) ? (gr + gi) : (gi - gr));
    }
    if (blockIdx.x == 0 && threadIdx.x < 32) {
        // dtype detect: int64 targets (<24) have zero odd 32-bit words
        int stride = (targets_raw[1] == 0 && targets_raw[3] == 0) ? 2 : 1;
        QS_tnorm[threadIdx.x] = targets_raw[threadIdx.x * stride];
    }
}

// IN_PLANAR: src is [2, 2^24] planar re/im. Otherwise interleaved float2.
// OUT_PLANAR: dst is planar. Otherwise interleaved float2.
template <int IN_PLANAR, int OUT_PLANAR>
__global__ __launch_bounds__(128, 9)
void qgate_kernel(const float* __restrict__ src,
                  float* __restrict__ dst,
                  int step) {
    const int tid = threadIdx.x;

    int q0 = cT[step * 4 + 0];
    int q1 = cT[step * 4 + 1];
    int q2 = cT[step * 4 + 2];
    int q3 = cT[step * 4 + 3];
    unsigned m0 = 1u << q0, m1 = 1u << q1, m2 = 1u << q2, m3 = 1u << q3;

    // sorted copy for ascending zero-bit insertion
    int a = q0, b = q1, c = q2, d = q3, t;
    if (a > b) { t = a; a = b; b = t; }
    if (c > d) { t = c; c = d; d = t; }
    if (a > c) { t = a; a = c; c = t; }
    if (b > d) { t = b; b = d; d = t; }
    if (b > c) { t = b; b = c; c = t; }

    unsigned g20 = blockIdx.x * 128u + tid;
    unsigned base = g20;
    base = ((base >> a) << (a + 1)) | (base & ((1u << a) - 1u));
    base = ((base >> b) << (b + 1)) | (base & ((1u << b) - 1u));
    base = ((base >> c) << (c + 1)) | (base & ((1u << c) - 1u));
    base = ((base >> d) << (d + 1)) | (base & ((1u << d) - 1u));

    const float* gbase = cGK + step * 768;
    const u64 NEG1 = pack2(-1.0f, -1.0f);
    const float2* s2 = reinterpret_cast<const float2*>(src);

#pragma unroll
    for (int quarter = 0; quarter < 4; quarter++) {
        u64 a1[4], a2[4], a3[4];
#pragma unroll
        for (int kc = 0; kc < 4; kc++) {
            // k-chunk kc covers amplitudes k = 4kc .. 4kc+3
            // (k bit0->m0, bit1->m1, bit2->m2, bit3->m3)
            unsigned ob = base + ((kc & 1) ? m2 : 0u) + ((kc & 2) ? m3 : 0u);
            unsigned oL0 = ob, oL1 = ob + m0;          // k-pair 2kc
            unsigned oH0 = ob + m1, oH1 = oH0 + m0;    // k-pair 2kc+1
            float rL0, iL0, rL1, iL1, rH0, iH0, rH1, iH1;
            if (IN_PLANAR) {
                rL0 = src[oL0]; iL0 = src[NSTATE + oL0];
                rL1 = src[oL1]; iL1 = src[NSTATE + oL1];
                rH0 = src[oH0]; iH0 = src[NSTATE + oH0];
                rH1 = src[oH1]; iH1 = src[NSTATE + oH1];
            } else {
                float2 vL0 = s2[oL0], vL1 = s2[oL1];
                float2 vH0 = s2[oH0], vH1 = s2[oH1];
                rL0 = vL0.x; iL0 = vL0.y; rL1 = vL1.x; iL1 = vL1.y;
                rH0 = vH0.x; iH0 = vH0.y; rH1 = vH1.x; iH1 = vH1.y;
            }
            u64 srL = pack2(rL0, rL1);
            u64 siL = pack2(iL0, iL1);
            u64 uL  = add2(srL, siL);
            u64 srH = pack2(rH0, rH1);
            u64 siH = pack2(iH0, iH1);
            u64 uH  = add2(srH, siH);

#pragma unroll
            for (int jj = 0; jj < 4; jj++) {
                int j = quarter * 4 + jj;
                // table quad for row j, k-chunk kc (uniform LDCU.128;
                // .x/.y ARE the packed f32x2 pairs for k-pairs 2kc, 2kc+1)
                ulonglong2 av = reinterpret_cast<const ulonglong2*>(gbase + j * 16)[kc];
                ulonglong2 bv = reinterpret_cast<const ulonglong2*>(gbase + 256 + j * 16)[kc];
                ulonglong2 cv = reinterpret_cast<const ulonglong2*>(gbase + 512 + j * 16)[kc];
                if (kc == 0) {
                    a1[jj] = mul2(av.x, uL);    // gr*(sr+si)
                    a2[jj] = mul2(bv.x, siL);   // (gr+gi)*si
                    a3[jj] = mul2(cv.x, srL);   // (gi-gr)*sr
                } else {
                    fma2_acc(a1[jj], av.x, uL);
                    fma2_acc(a2[jj], bv.x, siL);
                    fma2_acc(a3[jj], cv.x, srL);
                }
                fma2_acc(a1[jj], av.y, uH);
                fma2_acc(a2[jj], bv.y, siH);
                fma2_acc(a3[jj], cv.y, srH);
            }
        }
        // epilogue for this quarter's 4 outputs
#pragma unroll
        for (int jj = 0; jj < 4; jj++) {
            int j = quarter * 4 + jj;
            u64 dim = add2(a1[jj], a3[jj]);   // im pair = a1 + a3
            fma2_acc(a1[jj], a2[jj], NEG1);   // re pair = a1 - a2
            float rl, rh, il, ih;
            unpack2(a1[jj], rl, rh);
            unpack2(dim, il, ih);
            float re = rl + rh;
            float im = il + ih;
            unsigned oj = base + ((j & 1) ? m0 : 0u) + ((j & 2) ? m1 : 0u) +
                          ((j & 4) ? m2 : 0u) + ((j & 8) ? m3 : 0u);
            if (OUT_PLANAR) {
                dst[oj] = re;
                dst[NSTATE + oj] = im;
            } else {
                reinterpret_cast<float2*>(dst)[oj] = make_float2(re, im);
            }
        }
    }
}

extern "C" void kernel_launch(void* const* d_in, const int* in_sizes, int n_in,
                              void* d_out, int out_size) {
    const float* state   = (const float*)d_in[0];
    const int*   targets = (const int*)d_in[1];
    const float* gates   = (const float*)d_in[2];
    float*       out     = (float*)d_out;

    void* scratch_ptr = nullptr;
    cudaGetSymbolAddress(&scratch_ptr, QS_scratch);
    float* scratch = (float*)scratch_ptr;

    void* tables_ptr = nullptr;
    cudaGetSymbolAddress(&tables_ptr, QS_tables);
    void* tnorm_ptr = nullptr;
    cudaGetSymbolAddress(&tnorm_ptr, QS_tnorm);

    // build Karatsuba tables + normalized targets, upload to constant
    // memory (DtoD async, graph-capture-safe)
    qprep_kernel<<<NSTEPS, 256>>>(gates, targets);
    cudaMemcpyToSymbolAsync(cGK, tables_ptr, NSTEPS * 768 * sizeof(float), 0,
                            cudaMemcpyDeviceToDevice);
    cudaMemcpyToSymbolAsync(cT, tnorm_ptr, 32 * sizeof(int), 0,
                            cudaMemcpyDeviceToDevice);

    dim3 block(128);
    dim3 grid(NGROUPS / 128);  // 8192 blocks

    // step 0: planar input -> interleaved scratch
    qgate_kernel<1, 0><<<grid, block>>>(state, scratch, 0);
    // steps 1..6: interleaved in-place (each thread owns its group)
    for (int s = 1; s < NSTEPS - 1; s++) {
        qgate_kernel<0, 0><<<grid, block>>>(scratch, scratch, s);
    }
    // step 7: interleaved -> planar output
    qgate_kernel<0, 1><<<grid, block>>>(scratch, out, NSTEPS - 1);
}